// round 16
// baseline (speedup 1.0000x reference)
#include <cuda_runtime.h>
#include <cuda_fp16.h>
#include <cuda_bf16.h>
#include <cstdint>

// KANLayer: out[b] = sum_{d,h} tanh(x[b,d]*w1[d,h] + b1[d,h]) * w2[d,h] + sum_d b2[d]
// B=65536, D=256, H=16.
//
// R15 arithmetic kept EXACTLY (f16x2 w1/b1 + tanh.approx.f16x2, fp32 w2 and
// fp32 accumulation) -- this round changes only the execution shape:
//   TPB=256, 128 rows/block, grid=512 (fully resident, single wave),
//   __launch_bounds__(256,4): 4 blocks/SM -> 32 warps/SM (was 20).
//   TILE_D=8 double-buffered cp.async x tiles (smem 44 KB < 48 KB static cap).
// Discriminates latency-bound (expect ~50us) vs hidden-MUFU-floor (~65us).

#define D_DIM 256
#define H_DIM 16
#define DH    (D_DIM * H_DIM)   // 4096
#define B_DIM 65536
#define TPB   256               // 64 quads * 2 rows = 128 rows/block
#define ROWS_PER_BLOCK 128      // grid = 512
#define TILE_D 8                // d-values per x tile
#define NT (D_DIM / TILE_D)     // 32 tiles
#define XPITCH (TILE_D + 4)     // 12 floats = 48B pitch (16B aligned)

__device__ __forceinline__ __half2 htanh2(__half2 v) {
    unsigned vi = *reinterpret_cast<unsigned*>(&v);
    unsigned ro;
    asm("tanh.approx.f16x2 %0, %1;" : "=r"(ro) : "r"(vi));
    return *reinterpret_cast<__half2*>(&ro);
}

__device__ __forceinline__ void cp_async16(void* sdst, const void* gsrc) {
    uint32_t s = (uint32_t)__cvta_generic_to_shared(sdst);
    asm volatile("cp.async.cg.shared.global [%0], [%1], 16;" :: "r"(s), "l"(gsrc));
}
__device__ __forceinline__ void cp_commit() {
    asm volatile("cp.async.commit_group;");
}
template <int N> __device__ __forceinline__ void cp_wait() {
    asm volatile("cp.async.wait_group %0;" :: "n"(N));
}

__global__ __launch_bounds__(TPB, 4) void kan_main(const float* __restrict__ x,
                                                   const float* __restrict__ w1,
                                                   const float* __restrict__ b1,
                                                   const float* __restrict__ w2,
                                                   const float* __restrict__ b2,
                                                   float* __restrict__ out) {
    // s_wb[d*4+p] = {w1h2(4p,4p+1), w1h2(4p+2,4p+3), b1h2(4p,4p+1), b1h2(4p+2,4p+3)}
    __shared__ uint4 s_wb[D_DIM * 4];                      // 16 KB
    __shared__ float s_w2[DH];                             // 16 KB
    __shared__ float s_x[2][ROWS_PER_BLOCK][XPITCH];       // 12 KB
    __shared__ float s_red[8];
    // total ~44 KB static (< 48 KB cap); 4 blocks/SM -> 176 KB of 228 KB

    const int t    = threadIdx.x;
    const int lane = t & 31;
    const int wid  = t >> 5;
    const int p    = t & 3;          // h-quadrant
    const int g    = t >> 2;         // row group [0,64)

    // ---- Sum(b2): fixed-order deterministic reduce (256 elems, 256 threads).
    float myb2 = b2[t];
    #pragma unroll
    for (int off = 16; off > 0; off >>= 1)
        myb2 += __shfl_xor_sync(0xFFFFFFFFu, myb2, off);
    if (lane == 0) s_red[wid] = myb2;
    __syncthreads();
    float C = 0.0f;
    #pragma unroll
    for (int i = 0; i < 8; ++i) C += s_red[i];

    // ---- Stage params: interleave w1|b1 as f16 pairs, w2 as fp32.
    {
        const float4* gw1 = reinterpret_cast<const float4*>(w1);
        const float4* gb1 = reinterpret_cast<const float4*>(b1);
        const float4* gw2 = reinterpret_cast<const float4*>(w2);
        float4* sw2 = reinterpret_cast<float4*>(s_w2);
        #pragma unroll
        for (int i = t; i < DH / 4; i += TPB) {
            float4 a  = gw1[i];
            float4 bb = gb1[i];
            __half2 w10 = __floats2half2_rn(a.x, a.y);
            __half2 w11 = __floats2half2_rn(a.z, a.w);
            __half2 b10 = __floats2half2_rn(bb.x, bb.y);
            __half2 b11 = __floats2half2_rn(bb.z, bb.w);
            uint4 packed;
            packed.x = *reinterpret_cast<unsigned*>(&w10);
            packed.y = *reinterpret_cast<unsigned*>(&w11);
            packed.z = *reinterpret_cast<unsigned*>(&b10);
            packed.w = *reinterpret_cast<unsigned*>(&b11);
            s_wb[i] = packed;
            sw2[i] = gw2[i];
        }
    }

    const int row_base = blockIdx.x * ROWS_PER_BLOCK;

    // ---- x tile loader: 128 rows x 8 d = 4 KB = 256 x 16B chunks, 1/thread.
    // Warp covers 16 rows x 32B contiguous (sector-aligned).
    auto load_tile = [&](int tile, int buf) {
        const int rowL = t >> 1;
        const int c    = t & 1;
        cp_async16(&s_x[buf][rowL][c * 4],
                   x + (size_t)(row_base + rowL) * D_DIM + tile * TILE_D + c * 4);
        cp_commit();
    };

    load_tile(0, 0);
    __syncthreads();   // param staging visible before compute

    const int r0L = g * 2;
    const int r1L = g * 2 + 1;

    float a00 = 0.f, a01 = 0.f, a02 = 0.f, a03 = 0.f;   // row0, h = 4p..4p+3
    float a10 = 0.f, a11 = 0.f, a12 = 0.f, a13 = 0.f;   // row1

    for (int tile = 0; tile < NT; ++tile) {
        const int buf = tile & 1;
        if (tile + 1 < NT) {
            load_tile(tile + 1, buf ^ 1);
            cp_wait<1>();    // this tile's data landed (one newer group pending)
        } else {
            cp_wait<0>();
        }
        __syncthreads();

        const int dbase = tile * TILE_D;
        #pragma unroll
        for (int q4 = 0; q4 < TILE_D / 4; ++q4) {
            const float4 xv0 = *reinterpret_cast<const float4*>(&s_x[buf][r0L][q4 * 4]);
            const float4 xv1 = *reinterpret_cast<const float4*>(&s_x[buf][r1L][q4 * 4]);
            #pragma unroll
            for (int j = 0; j < 4; ++j) {
                const float xd0 = (j == 0) ? xv0.x : (j == 1) ? xv0.y : (j == 2) ? xv0.z : xv0.w;
                const float xd1 = (j == 0) ? xv1.x : (j == 1) ? xv1.y : (j == 2) ? xv1.z : xv1.w;
                const int d = dbase + q4 * 4 + j;

                const uint4  wb  = s_wb[d * 4 + p];
                const float4 w2v = *reinterpret_cast<const float4*>(&s_w2[d * H_DIM + p * 4]);

                const __half2 w10 = *reinterpret_cast<const __half2*>(&wb.x);
                const __half2 w11 = *reinterpret_cast<const __half2*>(&wb.y);
                const __half2 b10 = *reinterpret_cast<const __half2*>(&wb.z);
                const __half2 b11 = *reinterpret_cast<const __half2*>(&wb.w);

                const __half2 xx0 = __float2half2_rn(xd0);
                const __half2 xx1 = __float2half2_rn(xd1);

                const __half2 t00 = htanh2(__hfma2(xx0, w10, b10));
                const __half2 t01 = htanh2(__hfma2(xx0, w11, b11));
                const __half2 t10 = htanh2(__hfma2(xx1, w10, b10));
                const __half2 t11 = htanh2(__hfma2(xx1, w11, b11));

                const float2 f00 = __half22float2(t00);
                const float2 f01 = __half22float2(t01);
                const float2 f10 = __half22float2(t10);
                const float2 f11 = __half22float2(t11);

                a00 = fmaf(w2v.x, f00.x, a00);
                a01 = fmaf(w2v.y, f00.y, a01);
                a02 = fmaf(w2v.z, f01.x, a02);
                a03 = fmaf(w2v.w, f01.y, a03);

                a10 = fmaf(w2v.x, f10.x, a10);
                a11 = fmaf(w2v.y, f10.y, a11);
                a12 = fmaf(w2v.z, f11.x, a12);
                a13 = fmaf(w2v.w, f11.y, a13);
            }
        }
        __syncthreads();   // all threads done with buf before it is refilled
    }

    // ---- Combine 4 accumulators per row, then the 4 lanes of the quad.
    float s0 = (a00 + a01) + (a02 + a03);
    float s1 = (a10 + a11) + (a12 + a13);
    s0 += __shfl_xor_sync(0xFFFFFFFFu, s0, 1);
    s0 += __shfl_xor_sync(0xFFFFFFFFu, s0, 2);
    s1 += __shfl_xor_sync(0xFFFFFFFFu, s1, 1);
    s1 += __shfl_xor_sync(0xFFFFFFFFu, s1, 2);

    if (p == 0) {
        const int row0 = row_base + g * 2;
        out[row0]     = s0 + C;
        out[row0 + 1] = s1 + C;
    }
}

extern "C" void kernel_launch(void* const* d_in, const int* in_sizes, int n_in,
                              void* d_out, int out_size) {
    const float* x  = (const float*)d_in[0];
    const float* w1 = (const float*)d_in[1];
    const float* b1 = (const float*)d_in[2];
    const float* w2 = (const float*)d_in[3];
    const float* b2 = (const float*)d_in[4];
    float* out = (float*)d_out;

    kan_main<<<B_DIM / ROWS_PER_BLOCK, TPB>>>(x, w1, b1, w2, b2, out);
}

// round 17
// speedup vs baseline: 1.0492x; 1.0492x over previous
#include <cuda_runtime.h>
#include <cuda_fp16.h>
#include <cuda_bf16.h>
#include <cstdint>

// KANLayer: out[b] = sum_{d,h} tanh(x[b,d]*w1[d,h] + b1[d,h]) * w2[d,h] + sum_d b2[d]
// B=65536, D=256, H=16.
//
// Model (fits R4..R16): MUFU TANH throughput = 0.125 results/SMSP-cyc in both
// f32 (rt8) and f16x2 (rt16) forms -> floor ~57.5us regardless of packing.
// So: f32 args+tanh (precision back to ~1e-4), w2 stored f16x2 (smem 40KB ->
// 5 blocks/SM), NO smem-x / NO mainloop barriers -- x register-prefetched
// 1 iteration (4 d) ahead so DRAM latency sits behind ~256 warp-cycles of
// MUFU work. Quad h-split, 2 rows/thread.

#define D_DIM 256
#define H_DIM 16
#define DH    (D_DIM * H_DIM)   // 4096
#define B_DIM 65536
#define TPB   128               // 32 quads * 2 rows = 64 rows/block
#define ROWS_PER_BLOCK 64       // grid = 1024

__device__ __forceinline__ float ftanh(float v) {
    float r; asm("tanh.approx.f32 %0, %1;" : "=f"(r) : "f"(v)); return r;
}

__global__ __launch_bounds__(TPB) void kan_main(const float* __restrict__ x,
                                                const float* __restrict__ w1,
                                                const float* __restrict__ b1,
                                                const float* __restrict__ w2,
                                                const float* __restrict__ b2,
                                                float* __restrict__ out) {
    __shared__ float    s_w1[DH];        // 16 KB fp32
    __shared__ float    s_b1[DH];        // 16 KB fp32
    __shared__ unsigned s_w2[DH / 2];    // 8 KB f16x2 pairs
    // 40 KB -> 5 blocks/SM (200KB of 228KB)

    const int t    = threadIdx.x;
    const int lane = t & 31;
    const int wid  = t >> 5;
    const int p    = t & 3;          // h-quadrant: owns h in [4p, 4p+4)
    const int g    = t >> 2;         // row group [0,32)

    // ---- Sum(b2): fixed-order deterministic reduce (256 elems, 128 thr).
    // Uses s_w1[0..3] as transient scratch before param staging.
    float myb2 = b2[t] + b2[t + 128];
    #pragma unroll
    for (int off = 16; off > 0; off >>= 1)
        myb2 += __shfl_xor_sync(0xFFFFFFFFu, myb2, off);
    if (lane == 0) s_w1[wid] = myb2;
    __syncthreads();
    const float C = (s_w1[0] + s_w1[1]) + (s_w1[2] + s_w1[3]);
    __syncthreads();

    // ---- Stage params: w1/b1 fp32 verbatim, w2 packed to f16x2.
    {
        const float4* gw1 = reinterpret_cast<const float4*>(w1);
        const float4* gb1 = reinterpret_cast<const float4*>(b1);
        const float4* gw2 = reinterpret_cast<const float4*>(w2);
        float4* sw1 = reinterpret_cast<float4*>(s_w1);
        float4* sb1 = reinterpret_cast<float4*>(s_b1);
        uint2*  sw2 = reinterpret_cast<uint2*>(s_w2);
        #pragma unroll
        for (int i = t; i < DH / 4; i += TPB) {
            sw1[i] = gw1[i];
            sb1[i] = gb1[i];
            float4 c = gw2[i];
            __half2 h0 = __floats2half2_rn(c.x, c.y);
            __half2 h1 = __floats2half2_rn(c.z, c.w);
            uint2 u;
            u.x = *reinterpret_cast<unsigned*>(&h0);
            u.y = *reinterpret_cast<unsigned*>(&h1);
            sw2[i] = u;
        }
    }
    __syncthreads();

    // ---- Two rows per thread; x prefetched one d4-iteration ahead.
    const int row_base = blockIdx.x * ROWS_PER_BLOCK;
    const int row0 = row_base + g * 2;
    const float4* xr0 = reinterpret_cast<const float4*>(x) + (size_t)row0 * (D_DIM / 4);
    const float4* xr1 = xr0 + (D_DIM / 4);

    float a00 = 0.f, a01 = 0.f, a02 = 0.f, a03 = 0.f;   // row0, h = 4p..4p+3
    float a10 = 0.f, a11 = 0.f, a12 = 0.f, a13 = 0.f;   // row1

    float4 c0 = xr0[0];
    float4 c1 = xr1[0];

    for (int d4 = 0; d4 < D_DIM / 4; ++d4) {
        // Prefetch next iteration's x (clamped index; dead value on last iter)
        const int nx = (d4 + 1 < D_DIM / 4) ? d4 + 1 : d4;
        const float4 n0 = xr0[nx];
        const float4 n1 = xr1[nx];

        #pragma unroll
        for (int j = 0; j < 4; ++j) {
            const float xd0 = (j == 0) ? c0.x : (j == 1) ? c0.y : (j == 2) ? c0.z : c0.w;
            const float xd1 = (j == 0) ? c1.x : (j == 1) ? c1.y : (j == 2) ? c1.z : c1.w;
            const int d = d4 * 4 + j;

            const float4 w1v = *reinterpret_cast<const float4*>(&s_w1[d * H_DIM + p * 4]);
            const float4 b1v = *reinterpret_cast<const float4*>(&s_b1[d * H_DIM + p * 4]);
            const uint2  w2u = *reinterpret_cast<const uint2*>(&s_w2[d * (H_DIM / 2) + p * 2]);

            const __half2 wh0 = *reinterpret_cast<const __half2*>(&w2u.x);
            const __half2 wh1 = *reinterpret_cast<const __half2*>(&w2u.y);
            const float2 wf0 = __half22float2(wh0);
            const float2 wf1 = __half22float2(wh1);

            const float t00 = ftanh(fmaf(xd0, w1v.x, b1v.x));
            const float t01 = ftanh(fmaf(xd0, w1v.y, b1v.y));
            const float t02 = ftanh(fmaf(xd0, w1v.z, b1v.z));
            const float t03 = ftanh(fmaf(xd0, w1v.w, b1v.w));

            const float t10 = ftanh(fmaf(xd1, w1v.x, b1v.x));
            const float t11 = ftanh(fmaf(xd1, w1v.y, b1v.y));
            const float t12 = ftanh(fmaf(xd1, w1v.z, b1v.z));
            const float t13 = ftanh(fmaf(xd1, w1v.w, b1v.w));

            a00 = fmaf(wf0.x, t00, a00);
            a01 = fmaf(wf0.y, t01, a01);
            a02 = fmaf(wf1.x, t02, a02);
            a03 = fmaf(wf1.y, t03, a03);

            a10 = fmaf(wf0.x, t10, a10);
            a11 = fmaf(wf0.y, t11, a11);
            a12 = fmaf(wf1.x, t12, a12);
            a13 = fmaf(wf1.y, t13, a13);
        }

        c0 = n0;
        c1 = n1;
    }

    // ---- Combine 4 accumulators per row, then the 4 lanes of the quad.
    float s0 = (a00 + a01) + (a02 + a03);
    float s1 = (a10 + a11) + (a12 + a13);
    s0 += __shfl_xor_sync(0xFFFFFFFFu, s0, 1);
    s0 += __shfl_xor_sync(0xFFFFFFFFu, s0, 2);
    s1 += __shfl_xor_sync(0xFFFFFFFFu, s1, 1);
    s1 += __shfl_xor_sync(0xFFFFFFFFu, s1, 2);

    if (p == 0) {
        out[row0]     = s0 + C;
        out[row0 + 1] = s1 + C;
    }
}

extern "C" void kernel_launch(void* const* d_in, const int* in_sizes, int n_in,
                              void* d_out, int out_size) {
    const float* x  = (const float*)d_in[0];
    const float* w1 = (const float*)d_in[1];
    const float* b1 = (const float*)d_in[2];
    const float* w2 = (const float*)d_in[3];
    const float* b2 = (const float*)d_in[4];
    float* out = (float*)d_out;

    kan_main<<<B_DIM / ROWS_PER_BLOCK, TPB>>>(x, w1, b1, w2, b2, out);
}